// round 8
// baseline (speedup 1.0000x reference)
#include <cuda_runtime.h>
#include <cstdint>

// Energy-distance loss, tf32 mma.m16n8k8 with K-augmented norms:
//   A' = [-2a, na_hi, na_lo, 1, 1, pad0...]  (K = 72)
//   B' = [ b,   1,    1, nb_hi, nb_lo, pad0...]
//   acc = na + nb - 2 a.b  -> dist = sqrt.approx(acc)
// One 64-row j-tile per CTA (4 CTAs/SM). Warp-per-row prep.
// Global sums in double, one atomic per CTA.

#define NROWS 16384
#define MROWS 4096
#define DDIM  64
#define KDIM  72      // 64 data + 5 norm/one slots + 3 zero pad (9 k-steps)

__device__ double   g_acc[3];
__device__ uint32_t g_latA[NROWS * KDIM];   // A-role rows, k-interleaved
__device__ uint32_t g_latB[NROWS * KDIM];   // B-role rows
__device__ uint32_t g_zA[MROWS * KDIM];
__device__ uint32_t g_zB[MROWS * KDIM];

// smem words: A 128x72, B 64x72, red[8]
static constexpr int STRIDE  = KDIM;                // 72 (==8 mod 32 -> conflict-free)
static constexpr int SM_B    = 128 * STRIDE;        // 9216
static constexpr int SM_RED  = SM_B + 64 * STRIDE;  // 13824
static constexpr int SM_WORDS = SM_RED + 8;         // 13832
static constexpr int SM_BYTES = SM_WORDS * 4;       // 55328

// grid split (j-tiles are 64 rows)
static constexpr int G_CROSS = 128 * 64;            // 8192
static constexpr int G_LSELF = 16512;               // sum_{bi<128}(256-2bi)
static constexpr int G_ZSELF = 1056;                // sum_{bi<32}(64-2bi)
static constexpr int G_ALL   = G_CROSS + G_LSELF + G_ZSELF;   // 25760

// ---------------------------------------------------------------------------
__device__ __forceinline__ uint32_t smem_u32(const void* p) {
    uint32_t a;
    asm("{ .reg .u64 t; cvta.to.shared.u64 t, %1; cvt.u32.u64 %0, t; }"
        : "=r"(a) : "l"(p));
    return a;
}
__device__ __forceinline__ void cp16(uint32_t saddr, const void* g) {
    asm volatile("cp.async.cg.shared.global [%0], [%1], 16;"
                 :: "r"(saddr), "l"(g));
}
__device__ __forceinline__ uint32_t to_tf32(float x) {
    uint32_t t;
    asm("cvt.rna.tf32.f32 %0, %1;" : "=r"(t) : "f"(x));
    return t;
}
__device__ __forceinline__ void mma_tf32(float* c, uint32_t a0, uint32_t a1,
                                         uint32_t a2, uint32_t a3,
                                         uint32_t b0, uint32_t b1) {
    asm volatile(
        "mma.sync.aligned.m16n8k8.row.col.f32.tf32.tf32.f32 "
        "{%0,%1,%2,%3}, {%4,%5,%6,%7}, {%8,%9}, {%0,%1,%2,%3};"
        : "+f"(c[0]), "+f"(c[1]), "+f"(c[2]), "+f"(c[3])
        : "r"(a0), "r"(a1), "r"(a2), "r"(a3), "r"(b0), "r"(b1));
}
__device__ __forceinline__ float sqrt_approx(float x) {
    float r;
    asm("sqrt.approx.f32 %0, %1;" : "=f"(r) : "f"(x));
    return r;
}

// k-interleave within each 8-col block: pairs (c, c+4) adjacent for LDS.64
__device__ __forceinline__ int ilv(int q) {
    return (q & ~7) + 2 * (q & 3) + ((q & 7) >> 2);
}

// ---------------------------------------------------------------------------
// prep: one WARP per row. Coalesced reads, shfl norm reduce, coalesced writes.
__global__ void prep_kernel(const float* __restrict__ lat,
                            const float* __restrict__ z) {
    const int gw = (blockIdx.x * blockDim.x + threadIdx.x) >> 5;
    const int lane = threadIdx.x & 31;
    if (gw == 0 && lane < 3) g_acc[lane] = 0.0;
    if (gw >= NROWS + MROWS) return;

    const float* src;
    uint32_t *dA, *dB;
    if (gw < NROWS) {
        src = lat + (size_t)gw * DDIM;
        dA = g_latA + (size_t)gw * KDIM;
        dB = g_latB + (size_t)gw * KDIM;
    } else {
        int rr = gw - NROWS;
        src = z + (size_t)rr * DDIM;
        dA = g_zA + (size_t)rr * KDIM;
        dB = g_zB + (size_t)rr * KDIM;
    }

    float x0 = src[lane];
    float x1 = src[lane + 32];
    float s = fmaf(x0, x0, x1 * x1);
#pragma unroll
    for (int off = 16; off; off >>= 1)
        s += __shfl_xor_sync(0xffffffffu, s, off);

    dA[ilv(lane)]      = to_tf32(-2.f * x0);
    dA[ilv(lane + 32)] = to_tf32(-2.f * x1);
    dB[ilv(lane)]      = to_tf32(x0);
    dB[ilv(lane + 32)] = to_tf32(x1);

    if (lane < 8) {
        uint32_t nh = to_tf32(s);
        uint32_t nl = to_tf32(s - __uint_as_float(nh));
        const uint32_t one = 0x3f800000u;
        uint32_t av = (lane == 0) ? nh : (lane == 1) ? nl : (lane < 4) ? one : 0u;
        uint32_t bv = (lane < 2) ? one : (lane == 2) ? nh : (lane == 3) ? nl : 0u;
        dA[ilv(64 + lane)] = av;
        dB[ilv(64 + lane)] = bv;
    }
}

// ---------------------------------------------------------------------------
// fused pair kernel. Segments:
//   [0, 8192)          cross: 128 i-tiles x 64 j-tiles
//   [8192, 24704)      latent self (triangular, jt >= 2*bi)
//   [24704, 25760)     z self (triangular)
// CTA: A tile 128 rows x one 64-row j-tile; 8 warps 4(m) x 2(n), warp 32x32.
__global__ __launch_bounds__(256, 4)
void pair_kernel() {
    extern __shared__ uint32_t smf[];
    uint32_t* sA = smf;
    uint32_t* sB = smf + SM_B;
    float* red = (float*)(smf + SM_RED);
    const uint32_t sbase = smem_u32(smf);

    const int tid = threadIdx.x, wid = tid >> 5, lane = tid & 31;
    const int wm = wid >> 1, wn = wid & 1;

    int bi, jt, accIdx;
    bool diag;
    const uint32_t *Abuf, *Bbuf;
    {
        int bid = blockIdx.x;
        if (bid < G_CROSS) {
            bi = bid >> 6; jt = bid & 63;
            Abuf = g_latA; Bbuf = g_zB; accIdx = 0; diag = false;
        } else if (bid < G_CROSS + G_LSELF) {
            int b = bid - G_CROSS;
            bi = 0;
            while (b >= 256 - 2 * bi) { b -= 256 - 2 * bi; bi++; }
            jt = 2 * bi + b;
            Abuf = g_latA; Bbuf = g_latB; accIdx = 1; diag = (b < 2);
        } else {
            int b = bid - (G_CROSS + G_LSELF);
            bi = 0;
            while (b >= 64 - 2 * bi) { b -= 64 - 2 * bi; bi++; }
            jt = 2 * bi + b;
            Abuf = g_zA; Bbuf = g_zB; accIdx = 2; diag = (b < 2);
        }
    }
    const int i0 = bi * 128;
    const int j0 = jt * 64;

    // ---- async fill: A 2304 cp16, B 1152 cp16 (rows are 18 uint4) ----
    {
        const char* Ag = (const char*)(Abuf + (size_t)i0 * KDIM);
        const char* Bg = (const char*)(Bbuf + (size_t)j0 * KDIM);
#pragma unroll
        for (int it = 0; it < 9; it++) {
            int lin = tid + it * 256;               // 0..2303
            int row = lin / 18, c = lin % 18;
            cp16(sbase + (uint32_t)(row * STRIDE + c * 4) * 4,
                 Ag + (size_t)row * KDIM * 4 + c * 16);
        }
#pragma unroll
        for (int it = 0; it < 4; it++) {
            int lin = tid + it * 256;               // 0..1023
            int row = lin / 18, c = lin % 18;
            cp16(sbase + (uint32_t)(SM_B + row * STRIDE + c * 4) * 4,
                 Bg + (size_t)row * KDIM * 4 + c * 16);
        }
        {
            int lin = 1024 + tid;                   // 1024..1151 (tid<128)
            if (tid < 128) {
                int row = lin / 18, c = lin % 18;
                cp16(sbase + (uint32_t)(SM_B + row * STRIDE + c * 4) * 4,
                     Bg + (size_t)row * KDIM * 4 + c * 16);
            }
        }
        asm volatile("cp.async.commit_group;");
        asm volatile("cp.async.wait_group 0;" ::: "memory");
    }
    __syncthreads();

    const int aBase = (wm * 32 + (lane >> 2)) * STRIDE + 2 * (lane & 3);
    const int bBase = (wn * 32 + (lane >> 2)) * STRIDE + 2 * (lane & 3);

    float acc[2][4][4];
#pragma unroll
    for (int mt = 0; mt < 2; mt++)
#pragma unroll
        for (int nt = 0; nt < 4; nt++)
#pragma unroll
            for (int e = 0; e < 4; e++) acc[mt][nt][e] = 0.f;

#pragma unroll
    for (int kb = 0; kb < 9; kb++) {
        const int ko = kb * 8;
        uint2 aLo[2], aHi[2];
#pragma unroll
        for (int mt = 0; mt < 2; mt++) {
            int o = aBase + mt * 16 * STRIDE + ko;
            aLo[mt] = *(const uint2*)(sA + o);
            aHi[mt] = *(const uint2*)(sA + o + 8 * STRIDE);
        }
        uint2 bv[4];
#pragma unroll
        for (int nt = 0; nt < 4; nt++)
            bv[nt] = *(const uint2*)(sB + bBase + nt * 8 * STRIDE + ko);
#pragma unroll
        for (int mt = 0; mt < 2; mt++)
#pragma unroll
            for (int nt = 0; nt < 4; nt++)
                mma_tf32(acc[mt][nt],
                         aLo[mt].x, aHi[mt].x, aLo[mt].y, aHi[mt].y,
                         bv[nt].x, bv[nt].y);
    }

    // ---- epilogue: acc IS sq; sqrt + accumulate (mask only on diag CTAs) ----
    float tot0 = 0.f, tot1 = 0.f;
    if (!diag) {
#pragma unroll
        for (int mt = 0; mt < 2; mt++)
#pragma unroll
            for (int nt = 0; nt < 4; nt++)
#pragma unroll
                for (int e = 0; e < 4; e += 2) {
                    tot0 += sqrt_approx(acc[mt][nt][e]);
                    tot1 += sqrt_approx(acc[mt][nt][e + 1]);
                }
    } else {
        const int ib = i0 + wm * 32 + (lane >> 2);
        const int jb = j0 + wn * 32 + (lane & 3) * 2;
#pragma unroll
        for (int mt = 0; mt < 2; mt++)
#pragma unroll
            for (int nt = 0; nt < 4; nt++)
#pragma unroll
                for (int e = 0; e < 4; e++) {
                    float dist = sqrt_approx(acc[mt][nt][e]);
                    int ii = ib + mt * 16 + (e >> 1) * 8;
                    int jj = jb + nt * 8 + (e & 1);
                    if (jj <= ii) dist = 0.f;   // strict upper; kills i==j NaN
                    if (e & 1) tot1 += dist; else tot0 += dist;
                }
    }

    // ---- block reduce, one double atomic per CTA ----
    float total = tot0 + tot1;
#pragma unroll
    for (int off = 16; off; off >>= 1)
        total += __shfl_xor_sync(0xffffffffu, total, off);
    if (lane == 0) red[wid] = total;
    __syncthreads();
    if (tid == 0) {
        double t = 0.0;
#pragma unroll
        for (int w = 0; w < 8; w++) t += (double)red[w];
        atomicAdd(&g_acc[accIdx], t);
    }
}

// ---------------------------------------------------------------------------
__global__ void finalize_kernel(float* out) {
    double a1 = g_acc[0] * (2.0 / ((double)NROWS * MROWS * DDIM));
    double b1 = g_acc[1] * (2.0 / ((double)NROWS * NROWS * DDIM));  // 2x: upper only
    double c1 = g_acc[2] * (2.0 / ((double)MROWS * MROWS * DDIM));
    out[0] = (float)(a1 - b1 - c1);
}

// ---------------------------------------------------------------------------
extern "C" void kernel_launch(void* const* d_in, const int* in_sizes, int n_in,
                              void* d_out, int out_size) {
    const float* lat = (const float*)d_in[0];
    const float* z   = (const float*)d_in[1];
    if (n_in >= 2 && in_sizes[0] == MROWS * DDIM && in_sizes[1] == NROWS * DDIM) {
        const float* t = lat; lat = z; z = t;
    }
    float* out = (float*)d_out;

    cudaFuncSetAttribute(pair_kernel,
                         cudaFuncAttributeMaxDynamicSharedMemorySize, SM_BYTES);

    prep_kernel<<<(32 * (NROWS + MROWS)) / 256, 256>>>(lat, z);
    pair_kernel<<<G_ALL, 256, SM_BYTES>>>();
    finalize_kernel<<<1, 1>>>(out);
}

// round 9
// speedup vs baseline: 1.2482x; 1.2482x over previous
#include <cuda_runtime.h>
#include <cstdint>

// Energy-distance loss, tf32 mma.m16n8k8 with K-augmented norms:
//   A' = [-2a, na_hi, na_lo, 1, 1, pad0...]  (K = 72)
//   B' = [ b,   1,    1, nb_hi, nb_lo, pad0...]
//   acc = na + nb - 2 a.b  -> dist = sqrt.approx(acc)
// CTA = A tile (128 rows) x two consecutive 64-row j-tiles, 3 CTAs/SM.
// Warp-per-row prep. Global sums in double, one atomic per CTA.

#define NROWS 16384
#define MROWS 4096
#define DDIM  64
#define KDIM  72      // 64 data + 5 norm/one slots + 3 zero pad (9 k-steps)

__device__ double   g_acc[3];
__device__ uint32_t g_latA[NROWS * KDIM];   // A-role rows, k-interleaved
__device__ uint32_t g_latB[NROWS * KDIM];   // B-role rows
__device__ uint32_t g_zA[MROWS * KDIM];
__device__ uint32_t g_zB[MROWS * KDIM];

// smem words: A 128x72, B 128x72 (two 64-row j-tiles), red[8]
static constexpr int STRIDE  = KDIM;                 // 72 (==8 mod 32: conflict-free)
static constexpr int SM_B    = 128 * STRIDE;         // 9216
static constexpr int SM_RED  = SM_B + 128 * STRIDE;  // 18432
static constexpr int SM_WORDS = SM_RED + 8;
static constexpr int SM_BYTES = SM_WORDS * 4;        // 73760

// grid split (j-tile PAIRS of 128 rows)
static constexpr int G_CROSS = 128 * 32;             // 4096
static constexpr int G_LSELF = 8256;                 // sum_{bi<128}(128-bi)
static constexpr int G_ZSELF = 528;                  // sum_{bi<32}(32-bi)
static constexpr int G_ALL   = G_CROSS + G_LSELF + G_ZSELF;   // 12880

// ---------------------------------------------------------------------------
__device__ __forceinline__ uint32_t smem_u32(const void* p) {
    uint32_t a;
    asm("{ .reg .u64 t; cvta.to.shared.u64 t, %1; cvt.u32.u64 %0, t; }"
        : "=r"(a) : "l"(p));
    return a;
}
__device__ __forceinline__ void cp16(uint32_t saddr, const void* g) {
    asm volatile("cp.async.cg.shared.global [%0], [%1], 16;"
                 :: "r"(saddr), "l"(g));
}
__device__ __forceinline__ uint32_t to_tf32(float x) {
    uint32_t t;
    asm("cvt.rna.tf32.f32 %0, %1;" : "=r"(t) : "f"(x));
    return t;
}
__device__ __forceinline__ void mma_tf32(float* c, uint32_t a0, uint32_t a1,
                                         uint32_t a2, uint32_t a3,
                                         uint32_t b0, uint32_t b1) {
    asm volatile(
        "mma.sync.aligned.m16n8k8.row.col.f32.tf32.tf32.f32 "
        "{%0,%1,%2,%3}, {%4,%5,%6,%7}, {%8,%9}, {%0,%1,%2,%3};"
        : "+f"(c[0]), "+f"(c[1]), "+f"(c[2]), "+f"(c[3])
        : "r"(a0), "r"(a1), "r"(a2), "r"(a3), "r"(b0), "r"(b1));
}
__device__ __forceinline__ float sqrt_approx(float x) {
    float r;
    asm("sqrt.approx.f32 %0, %1;" : "=f"(r) : "f"(x));
    return r;
}

// k-interleave within each 8-col block: pairs (c, c+4) adjacent for LDS.64
__device__ __forceinline__ int ilv(int q) {
    return (q & ~7) + 2 * (q & 3) + ((q & 7) >> 2);
}

// ---------------------------------------------------------------------------
// prep: one WARP per row. Coalesced reads, shfl norm reduce, coalesced writes.
__global__ void prep_kernel(const float* __restrict__ lat,
                            const float* __restrict__ z) {
    const int gw = (blockIdx.x * blockDim.x + threadIdx.x) >> 5;
    const int lane = threadIdx.x & 31;
    if (gw == 0 && lane < 3) g_acc[lane] = 0.0;
    if (gw >= NROWS + MROWS) return;

    const float* src;
    uint32_t *dA, *dB;
    if (gw < NROWS) {
        src = lat + (size_t)gw * DDIM;
        dA = g_latA + (size_t)gw * KDIM;
        dB = g_latB + (size_t)gw * KDIM;
    } else {
        int rr = gw - NROWS;
        src = z + (size_t)rr * DDIM;
        dA = g_zA + (size_t)rr * KDIM;
        dB = g_zB + (size_t)rr * KDIM;
    }

    float x0 = src[lane];
    float x1 = src[lane + 32];
    float s = fmaf(x0, x0, x1 * x1);
#pragma unroll
    for (int off = 16; off; off >>= 1)
        s += __shfl_xor_sync(0xffffffffu, s, off);

    dA[ilv(lane)]      = to_tf32(-2.f * x0);
    dA[ilv(lane + 32)] = to_tf32(-2.f * x1);
    dB[ilv(lane)]      = to_tf32(x0);
    dB[ilv(lane + 32)] = to_tf32(x1);

    if (lane < 8) {
        uint32_t nh = to_tf32(s);
        uint32_t nl = to_tf32(s - __uint_as_float(nh));
        const uint32_t one = 0x3f800000u;
        uint32_t av = (lane == 0) ? nh : (lane == 1) ? nl : (lane < 4) ? one : 0u;
        uint32_t bv = (lane < 2) ? one : (lane == 2) ? nh : (lane == 3) ? nl : 0u;
        dA[ilv(64 + lane)] = av;
        dB[ilv(64 + lane)] = bv;
    }
}

// ---------------------------------------------------------------------------
// fused pair kernel. Segments (j-tile pairs of 128 rows):
//   [0, 4096)        cross:   128 i-tiles x 32 pairs
//   [4096, 12352)    latent self (triangular, p >= bi, TP=128)
//   [12352, 12880)   z self (triangular, TP=32)
// CTA: A tile 128 rows x two consecutive 64-row j-tiles; 8 warps 4m x 2n.
__global__ __launch_bounds__(256, 3)
void pair_kernel() {
    extern __shared__ uint32_t smf[];
    uint32_t* sA = smf;
    uint32_t* sB = smf + SM_B;
    float* red = (float*)(smf + SM_RED);
    const uint32_t sbase = smem_u32(smf);

    const int tid = threadIdx.x, wid = tid >> 5, lane = tid & 31;
    const int wm = wid >> 1, wn = wid & 1;

    int bi, p, accIdx;
    bool self;
    const uint32_t *Abuf, *Bbuf;
    {
        int bid = blockIdx.x;
        if (bid < G_CROSS) {
            bi = bid >> 5; p = bid & 31;
            Abuf = g_latA; Bbuf = g_zB; accIdx = 0; self = false;
        } else if (bid < G_CROSS + G_LSELF) {
            int b = bid - G_CROSS;
            bi = 0;
            while (b >= 128 - bi) { b -= 128 - bi; bi++; }
            p = bi + b;
            Abuf = g_latA; Bbuf = g_latB; accIdx = 1; self = true;
        } else {
            int b = bid - (G_CROSS + G_LSELF);
            bi = 0;
            while (b >= 32 - bi) { b -= 32 - bi; bi++; }
            p = bi + b;
            Abuf = g_zA; Bbuf = g_zB; accIdx = 2; self = true;
        }
    }
    const int i0 = bi * 128;
    const int j0 = p * 128;
    const bool diag = self && (p == bi);

    // ---- async fill: A rows i0..+128, B rows j0..+128 (18 uint4/row) ----
    {
        const char* Ag = (const char*)(Abuf + (size_t)i0 * KDIM);
        const char* Bg = (const char*)(Bbuf + (size_t)j0 * KDIM);
#pragma unroll
        for (int it = 0; it < 9; it++) {
            int lin = tid + it * 256;            // 0..2303
            int row = lin / 18, c = lin % 18;
            uint32_t off = (uint32_t)(row * STRIDE + c * 4) * 4;
            cp16(sbase + off, Ag + (size_t)row * KDIM * 4 + c * 16);
            cp16(sbase + SM_B * 4 + off, Bg + (size_t)row * KDIM * 4 + c * 16);
        }
        asm volatile("cp.async.commit_group;");
        asm volatile("cp.async.wait_group 0;" ::: "memory");
    }
    __syncthreads();

    const int aBase = (wm * 32 + (lane >> 2)) * STRIDE + 2 * (lane & 3);
    const int bBase = (wn * 32 + (lane >> 2)) * STRIDE + 2 * (lane & 3);
    const int ib = i0 + wm * 32 + (lane >> 2);

    float tot0 = 0.f, tot1 = 0.f;

#pragma unroll
    for (int s = 0; s < 2; s++) {
        const uint32_t* sBt = sB + s * 64 * STRIDE;

        float acc[2][4][4];
#pragma unroll
        for (int mt = 0; mt < 2; mt++)
#pragma unroll
            for (int nt = 0; nt < 4; nt++)
#pragma unroll
                for (int e = 0; e < 4; e++) acc[mt][nt][e] = 0.f;

#pragma unroll
        for (int kb = 0; kb < 9; kb++) {
            const int ko = kb * 8;
            uint2 aLo[2], aHi[2];
#pragma unroll
            for (int mt = 0; mt < 2; mt++) {
                int o = aBase + mt * 16 * STRIDE + ko;
                aLo[mt] = *(const uint2*)(sA + o);
                aHi[mt] = *(const uint2*)(sA + o + 8 * STRIDE);
            }
            uint2 bv[4];
#pragma unroll
            for (int nt = 0; nt < 4; nt++)
                bv[nt] = *(const uint2*)(sBt + bBase + nt * 8 * STRIDE + ko);
#pragma unroll
            for (int mt = 0; mt < 2; mt++)
#pragma unroll
                for (int nt = 0; nt < 4; nt++)
                    mma_tf32(acc[mt][nt],
                             aLo[mt].x, aHi[mt].x, aLo[mt].y, aHi[mt].y,
                             bv[nt].x, bv[nt].y);
        }

        // ---- epilogue: acc IS sq; sqrt + accumulate ----
        if (!diag) {
#pragma unroll
            for (int mt = 0; mt < 2; mt++)
#pragma unroll
                for (int nt = 0; nt < 4; nt++)
#pragma unroll
                    for (int e = 0; e < 4; e += 2) {
                        tot0 += sqrt_approx(acc[mt][nt][e]);
                        tot1 += sqrt_approx(acc[mt][nt][e + 1]);
                    }
        } else {
            const int jb = j0 + s * 64 + wn * 32 + (lane & 3) * 2;
#pragma unroll
            for (int mt = 0; mt < 2; mt++)
#pragma unroll
                for (int nt = 0; nt < 4; nt++)
#pragma unroll
                    for (int e = 0; e < 4; e++) {
                        float dist = sqrt_approx(acc[mt][nt][e]);
                        int ii = ib + mt * 16 + (e >> 1) * 8;
                        int jj = jb + nt * 8 + (e & 1);
                        if (jj <= ii) dist = 0.f;   // strict upper; kills i==j NaN
                        if (e & 1) tot1 += dist; else tot0 += dist;
                    }
        }
    }

    // ---- block reduce, one double atomic per CTA ----
    float total = tot0 + tot1;
#pragma unroll
    for (int off = 16; off; off >>= 1)
        total += __shfl_xor_sync(0xffffffffu, total, off);
    if (lane == 0) red[wid] = total;
    __syncthreads();
    if (tid == 0) {
        double t = 0.0;
#pragma unroll
        for (int w = 0; w < 8; w++) t += (double)red[w];
        atomicAdd(&g_acc[accIdx], t);
    }
}

// ---------------------------------------------------------------------------
__global__ void finalize_kernel(float* out) {
    double a1 = g_acc[0] * (2.0 / ((double)NROWS * MROWS * DDIM));
    double b1 = g_acc[1] * (2.0 / ((double)NROWS * NROWS * DDIM));  // 2x: upper only
    double c1 = g_acc[2] * (2.0 / ((double)MROWS * MROWS * DDIM));
    out[0] = (float)(a1 - b1 - c1);
}

// ---------------------------------------------------------------------------
extern "C" void kernel_launch(void* const* d_in, const int* in_sizes, int n_in,
                              void* d_out, int out_size) {
    const float* lat = (const float*)d_in[0];
    const float* z   = (const float*)d_in[1];
    if (n_in >= 2 && in_sizes[0] == MROWS * DDIM && in_sizes[1] == NROWS * DDIM) {
        const float* t = lat; lat = z; z = t;
    }
    float* out = (float*)d_out;

    cudaFuncSetAttribute(pair_kernel,
                         cudaFuncAttributeMaxDynamicSharedMemorySize, SM_BYTES);

    prep_kernel<<<(32 * (NROWS + MROWS)) / 256, 256>>>(lat, z);
    pair_kernel<<<G_ALL, 256, SM_BYTES>>>();
    finalize_kernel<<<1, 1>>>(out);
}